// round 9
// baseline (speedup 1.0000x reference)
#include <cuda_runtime.h>
#include <cuda_fp16.h>

// ---------------- problem constants ----------------
#define N_NODES 16384
#define N_EDGES 524288
#define BATCH   32
#define DIM     64
#define OUTD    64
#define FEAT    (BATCH * DIM)   /* 2048 */
#define NMAT    5
#define WROWS   (DIM * NMAT)    /* 320 */
#define FCHUNK  1024            /* feature chunk (halves) per SpMM launch */
#define WPAD    328             /* smem W row stride (halves), conflict-free */
#define HALF_ROWS (BATCH / 2 * N_NODES)   /* 262144 GEMM rows per half */

// ---------------- device scratch (static: no allocations allowed) ----------
__device__ __align__(16) __half g_x[NMAT][(size_t)N_NODES * FEAT];  // ~335 MB
__device__ float g_inv_drow[N_NODES];
__device__ float g_inv_dcol[N_NODES];
__device__ int   g_cnt1[N_NODES];
__device__ int   g_cnt2[N_NODES];
__device__ int   g_rowptr1[N_NODES + 1];
__device__ int   g_rowptr2[N_NODES + 1];
__device__ int   g_pos1[N_NODES];
__device__ int   g_pos2[N_NODES];
__device__ int   g_adj_col[2][N_EDGES];
__device__ float g_adj_val[2][N_EDGES];

// ---------------- build kernels ----------------
__global__ void k_init() {
    int i = blockIdx.x * blockDim.x + threadIdx.x;
    if (i < N_NODES) {
        g_inv_drow[i] = 0.f;
        g_inv_dcol[i] = 0.f;
        g_cnt1[i] = 0;
        g_cnt2[i] = 0;
    }
}

__global__ void k_degree(const float* __restrict__ adj,
                         const int* __restrict__ rows,
                         const int* __restrict__ cols) {
    int e = blockIdx.x * blockDim.x + threadIdx.x;
    if (e < N_EDGES) {
        int r = rows[e], c = cols[e];
        float a = adj[e];
        atomicAdd(&g_inv_drow[r], a);
        atomicAdd(&g_inv_dcol[c], a);
        atomicAdd(&g_cnt1[c], 1);   // support1 CSR keyed by dst = cols
        atomicAdd(&g_cnt2[r], 1);   // support2 CSR keyed by dst = rows
    }
}

// single-block: invert degrees + warp-shuffle exclusive scan of both histograms
__global__ void k_scan() {
    __shared__ int warp_sums[32];
    int t = threadIdx.x;
    int lane = t & 31;
    int warp = t >> 5;

    for (int i = t; i < N_NODES; i += 1024) {
        float d = g_inv_drow[i]; g_inv_drow[i] = (d > 0.f) ? (1.f / d) : 0.f;
        float c = g_inv_dcol[i]; g_inv_dcol[i] = (c > 0.f) ? (1.f / c) : 0.f;
    }
    __syncthreads();

    #pragma unroll
    for (int s = 0; s < 2; s++) {
        const int* cnt = s ? g_cnt2 : g_cnt1;
        int* rowptr    = s ? g_rowptr2 : g_rowptr1;
        int* pos       = s ? g_pos2 : g_pos1;

        int base = t * 16;
        int local[16];
        int sum = 0;
        #pragma unroll
        for (int i = 0; i < 16; i++) { local[i] = sum; sum += cnt[base + i]; }

        int inc = sum;
        #pragma unroll
        for (int off = 1; off < 32; off <<= 1) {
            int v = __shfl_up_sync(0xffffffffu, inc, off);
            if (lane >= off) inc += v;
        }
        if (lane == 31) warp_sums[warp] = inc;
        __syncthreads();
        if (warp == 0) {
            int v = warp_sums[lane];
            #pragma unroll
            for (int off = 1; off < 32; off <<= 1) {
                int u = __shfl_up_sync(0xffffffffu, v, off);
                if (lane >= off) v += u;
            }
            warp_sums[lane] = v;
        }
        __syncthreads();
        int offset = (warp ? warp_sums[warp - 1] : 0) + (inc - sum);
        #pragma unroll
        for (int i = 0; i < 16; i++) {
            int p = offset + local[i];
            rowptr[base + i] = p;
            pos[base + i] = p;
        }
        if (t == 1023) rowptr[N_NODES] = warp_sums[31];
        __syncthreads();
    }
}

__global__ void k_fill(const float* __restrict__ adj,
                       const int* __restrict__ rows,
                       const int* __restrict__ cols) {
    int e = blockIdx.x * blockDim.x + threadIdx.x;
    if (e < N_EDGES) {
        int r = rows[e], c = cols[e];
        float a = adj[e];
        int s1 = atomicAdd(&g_pos1[c], 1);
        g_adj_col[0][s1] = r;
        g_adj_val[0][s1] = a * g_inv_drow[r];
        int s2 = atomicAdd(&g_pos2[r], 1);
        g_adj_col[1][s2] = c;
        g_adj_val[1][s2] = a * g_inv_dcol[c];
    }
}

// transpose + fp32->fp16: x0[n, b*64+d] = inputs[b, n, d]
__global__ void k_transpose(const float* __restrict__ in) {
    int idx = blockIdx.x * blockDim.x + threadIdx.x;   // over N*FEAT/8
    int f8 = idx & 255;
    int n  = idx >> 8;
    int f  = f8 << 3;
    int b  = f >> 6;
    int d  = f & 63;
    const float4* src = reinterpret_cast<const float4*>(
        in + ((size_t)b * N_NODES * DIM + (size_t)n * DIM + d));
    float4 v0 = src[0];
    float4 v1 = src[1];
    __half2 h[4];
    h[0] = __floats2half2_rn(v0.x, v0.y);
    h[1] = __floats2half2_rn(v0.z, v0.w);
    h[2] = __floats2half2_rn(v1.x, v1.y);
    h[3] = __floats2half2_rn(v1.z, v1.w);
    *reinterpret_cast<uint4*>(&g_x[0][(size_t)n * FEAT + f]) =
        *reinterpret_cast<uint4*>(h);
}

// ---------------- SpMM (CSR gather, fp16 storage / fp32 accumulate) -------
// out = (S @ xin)            if m_z < 0
// out = 2*(S @ xin) - xz     otherwise
__global__ void __launch_bounds__(128)
k_spmm(int support, int m_in, int m_z, int m_out, int chunk, int streamout) {
    const int* __restrict__ rowptr = support ? g_rowptr2 : g_rowptr1;
    const int* __restrict__ colidx = g_adj_col[support];
    const float* __restrict__ val  = g_adj_val[support];
    const __half* __restrict__ xin = g_x[m_in];
    __half* __restrict__ xout      = g_x[m_out];

    int n = blockIdx.x;
    int fbase = chunk * FCHUNK + (threadIdx.x << 3);   // 8 halves per thread

    int e   = rowptr[n];
    int end = rowptr[n + 1];

    float acc[8];
    #pragma unroll
    for (int i = 0; i < 8; i++) acc[i] = 0.f;

    for (; e + 4 <= end; e += 4) {
        int   c0 = colidx[e],     c1 = colidx[e + 1];
        int   c2 = colidx[e + 2], c3 = colidx[e + 3];
        float v0 = val[e],     v1 = val[e + 1];
        float v2 = val[e + 2], v3 = val[e + 3];
        uint4 r0 = *reinterpret_cast<const uint4*>(xin + (size_t)c0 * FEAT + fbase);
        uint4 r1 = *reinterpret_cast<const uint4*>(xin + (size_t)c1 * FEAT + fbase);
        uint4 r2 = *reinterpret_cast<const uint4*>(xin + (size_t)c2 * FEAT + fbase);
        uint4 r3 = *reinterpret_cast<const uint4*>(xin + (size_t)c3 * FEAT + fbase);
        const __half2* h0 = reinterpret_cast<const __half2*>(&r0);
        const __half2* h1 = reinterpret_cast<const __half2*>(&r1);
        const __half2* h2 = reinterpret_cast<const __half2*>(&r2);
        const __half2* h3 = reinterpret_cast<const __half2*>(&r3);
        #pragma unroll
        for (int i = 0; i < 4; i++) {
            float2 f0 = __half22float2(h0[i]);
            float2 f1 = __half22float2(h1[i]);
            float2 f2 = __half22float2(h2[i]);
            float2 f3 = __half22float2(h3[i]);
            acc[2 * i]     += v0 * f0.x + v1 * f1.x + v2 * f2.x + v3 * f3.x;
            acc[2 * i + 1] += v0 * f0.y + v1 * f1.y + v2 * f2.y + v3 * f3.y;
        }
    }
    for (; e < end; e++) {
        int   c0 = colidx[e];
        float v0 = val[e];
        uint4 r0 = *reinterpret_cast<const uint4*>(xin + (size_t)c0 * FEAT + fbase);
        const __half2* h0 = reinterpret_cast<const __half2*>(&r0);
        #pragma unroll
        for (int i = 0; i < 4; i++) {
            float2 f0 = __half22float2(h0[i]);
            acc[2 * i]     += v0 * f0.x;
            acc[2 * i + 1] += v0 * f0.y;
        }
    }

    size_t ooff = (size_t)n * FEAT + fbase;
    if (m_z >= 0) {
        uint4 rz = __ldcs(reinterpret_cast<const uint4*>(g_x[m_z] + ooff));
        const __half2* hz = reinterpret_cast<const __half2*>(&rz);
        #pragma unroll
        for (int i = 0; i < 4; i++) {
            float2 fz = __half22float2(hz[i]);
            acc[2 * i]     = 2.f * acc[2 * i]     - fz.x;
            acc[2 * i + 1] = 2.f * acc[2 * i + 1] - fz.y;
        }
    }

    __half2 hout[4];
    #pragma unroll
    for (int i = 0; i < 4; i++)
        hout[i] = __floats2half2_rn(acc[2 * i], acc[2 * i + 1]);
    if (streamout)
        __stcs(reinterpret_cast<uint4*>(xout + ooff),
               *reinterpret_cast<uint4*>(hout));
    else
        *reinterpret_cast<uint4*>(xout + ooff) = *reinterpret_cast<uint4*>(hout);
}

// ---------------- tensor-core output GEMM (half of rows) -----------------
// out[row, :] = sum_{k'} A[row, k'] * Wh[k', :] + bias
//   row = b*N + n ; k' = m*64 + d ; A[row, k'] = g_x[m][n*FEAT + b*64 + d]
__global__ void __launch_bounds__(256)
k_gemm(const float* __restrict__ W, const float* __restrict__ bias,
       float* __restrict__ out, int row_base) {
    __shared__ __half swh[OUTD][WPAD];   // [n][k'], padded: 42 KB

    for (int i = threadIdx.x; i < WROWS * OUTD; i += 256) {
        int kp = i >> 6;          // k' = m*64+d
        int n  = i & 63;
        int d  = kp & 63;
        int m  = kp >> 6;
        swh[n][kp] = __float2half(W[(d * NMAT + m) * OUTD + n]);
    }
    __syncthreads();

    int warp = threadIdx.x >> 5;
    int lane = threadIdx.x & 31;
    int g = lane >> 2;            // 0..7
    int q = lane & 3;             // 0..3

    int rowbase = row_base + (blockIdx.x * 8 + warp) * 16;
    int b = rowbase >> 14;
    int node0 = rowbase & 16383;

    float acc[8][4];
    #pragma unroll
    for (int nt = 0; nt < 8; nt++) {
        float b0 = __ldg(bias + nt * 8 + 2 * q);
        float b1 = __ldg(bias + nt * 8 + 2 * q + 1);
        acc[nt][0] = b0; acc[nt][1] = b1;
        acc[nt][2] = b0; acc[nt][3] = b1;
    }

    #pragma unroll 1
    for (int m = 0; m < NMAT; m++) {
        const __half* xm = g_x[m] + (size_t)node0 * FEAT + b * DIM;
        #pragma unroll
        for (int ds = 0; ds < 4; ds++) {
            int d0 = ds * 16;
            const __half* base = xm + d0;
            unsigned a0 = *reinterpret_cast<const unsigned*>(base + (size_t)g * FEAT + 2 * q);
            unsigned a1 = *reinterpret_cast<const unsigned*>(base + (size_t)(g + 8) * FEAT + 2 * q);
            unsigned a2 = *reinterpret_cast<const unsigned*>(base + (size_t)g * FEAT + 2 * q + 8);
            unsigned a3 = *reinterpret_cast<const unsigned*>(base + (size_t)(g + 8) * FEAT + 2 * q + 8);
            int kp = m * 64 + d0;
            #pragma unroll
            for (int nt = 0; nt < 8; nt++) {
                int n = nt * 8 + g;
                unsigned b0 = *reinterpret_cast<const unsigned*>(&swh[n][kp + 2 * q]);
                unsigned b1 = *reinterpret_cast<const unsigned*>(&swh[n][kp + 2 * q + 8]);
                asm volatile(
                    "mma.sync.aligned.m16n8k16.row.col.f32.f16.f16.f32 "
                    "{%0,%1,%2,%3}, {%4,%5,%6,%7}, {%8,%9}, {%0,%1,%2,%3};\n"
                    : "+f"(acc[nt][0]), "+f"(acc[nt][1]),
                      "+f"(acc[nt][2]), "+f"(acc[nt][3])
                    : "r"(a0), "r"(a1), "r"(a2), "r"(a3), "r"(b0), "r"(b1));
            }
        }
    }

    #pragma unroll
    for (int nt = 0; nt < 8; nt++) {
        size_t o0 = (size_t)(rowbase + g) * OUTD + nt * 8 + 2 * q;
        size_t o1 = (size_t)(rowbase + g + 8) * OUTD + nt * 8 + 2 * q;
        *reinterpret_cast<float2*>(out + o0) = make_float2(acc[nt][0], acc[nt][1]);
        *reinterpret_cast<float2*>(out + o1) = make_float2(acc[nt][2], acc[nt][3]);
    }
}

// ---------------- launch ----------------
extern "C" void kernel_launch(void* const* d_in, const int* in_sizes, int n_in,
                              void* d_out, int out_size) {
    const float* inputs  = (const float*)d_in[0];
    const float* adj     = (const float*)d_in[1];
    const int*   rows    = (const int*)d_in[2];
    const int*   cols    = (const int*)d_in[3];
    const float* weights = (const float*)d_in[4];
    const float* biases  = (const float*)d_in[5];
    float*       out     = (float*)d_out;

    static cudaStream_t s2 = 0;
    static cudaEvent_t ev0 = 0, evT = 0, evJ = 0;
    static cudaEvent_t evC[2];
    if (!s2) {
        cudaStreamCreateWithFlags(&s2, cudaStreamNonBlocking);
        cudaEventCreateWithFlags(&ev0, cudaEventDisableTiming);
        cudaEventCreateWithFlags(&evT, cudaEventDisableTiming);
        cudaEventCreateWithFlags(&evJ, cudaEventDisableTiming);
        cudaEventCreateWithFlags(&evC[0], cudaEventDisableTiming);
        cudaEventCreateWithFlags(&evC[1], cudaEventDisableTiming);
    }

    // fork: transpose (writes g_x[0]) runs concurrent with CSR build
    cudaEventRecord(ev0, 0);
    cudaStreamWaitEvent(s2, ev0, 0);
    k_transpose<<<(N_NODES * (FEAT / 8)) / 256, 256, 0, s2>>>(inputs);
    cudaEventRecord(evT, s2);

    k_init<<<(N_NODES + 255) / 256, 256>>>();
    k_degree<<<N_EDGES / 256, 256>>>(adj, rows, cols);
    k_scan<<<1, 1024>>>();
    k_fill<<<N_EDGES / 256, 256>>>(adj, rows, cols);
    cudaStreamWaitEvent(0, evT, 0);

    // chunk c covers batches 16c..16c+15; after chunk c's chain, GEMM rows
    // [c*HALF_ROWS, (c+1)*HALF_ROWS) are final -> overlap that GEMM half
    // with the next chunk's LTS-bound chain (tiny 35us HMMA kernel).
    for (int c = 0; c < FEAT / FCHUNK; c++) {
        // xs[1] = S1 @ x0
        k_spmm<<<N_NODES, 128>>>(0, 0, -1, 1, c, 0);
        // xs[2] = 2*S1@xs[1] - x0
        k_spmm<<<N_NODES, 128>>>(0, 1, 0, 2, c, 1);
        // xs[3] = S2 @ xs[1]   (x0 deliberately not reset between supports)
        k_spmm<<<N_NODES, 128>>>(1, 1, -1, 3, c, 0);
        // xs[4] = 2*S2@xs[3] - xs[1]
        k_spmm<<<N_NODES, 128>>>(1, 3, 1, 4, c, 1);
        cudaEventRecord(evC[c], 0);

        cudaStreamWaitEvent(s2, evC[c], 0);
        k_gemm<<<HALF_ROWS / 128, 256, 0, s2>>>(weights, biases, out,
                                                c * HALF_ROWS);
    }

    cudaEventRecord(evJ, s2);
    cudaStreamWaitEvent(0, evJ, 0);
}

// round 10
// speedup vs baseline: 1.0561x; 1.0561x over previous
#include <cuda_runtime.h>
#include <cuda_fp16.h>

// ---------------- problem constants ----------------
#define N_NODES 16384
#define N_EDGES 524288
#define BATCH   32
#define DIM     64
#define OUTD    64
#define FEAT    (BATCH * DIM)   /* 2048 */
#define NMAT    5
#define WROWS   (DIM * NMAT)    /* 320 */
#define FCHUNK  1024            /* feature chunk (halves) per SpMM launch */
#define WPAD    328             /* smem W row stride (halves), conflict-free */
#define HALF_ROWS (BATCH / 2 * N_NODES)   /* 262144 GEMM rows per half */
#define SCAN_BLKS 16            /* blocks in k_scan_local (1024 nodes each) */

// ---------------- device scratch (static: no allocations allowed) ----------
__device__ __align__(16) __half g_x[NMAT][(size_t)N_NODES * FEAT];  // ~335 MB
__device__ float g_inv_drow[N_NODES];
__device__ float g_inv_dcol[N_NODES];
__device__ int   g_cnt1[N_NODES];
__device__ int   g_cnt2[N_NODES];
__device__ int   g_rowptr1[N_NODES + 1];
__device__ int   g_rowptr2[N_NODES + 1];
__device__ int   g_pos1[N_NODES];
__device__ int   g_pos2[N_NODES];
__device__ int   g_bsum[2][SCAN_BLKS];
__device__ int   g_adj_col[2][N_EDGES];
__device__ float g_adj_val[2][N_EDGES];

// ---------------- build kernels ----------------
__global__ void k_init() {
    int i = blockIdx.x * blockDim.x + threadIdx.x;
    if (i < N_NODES) {
        g_inv_drow[i] = 0.f;
        g_inv_dcol[i] = 0.f;
        g_cnt1[i] = 0;
        g_cnt2[i] = 0;
    }
}

__global__ void k_degree(const float* __restrict__ adj,
                         const int* __restrict__ rows,
                         const int* __restrict__ cols) {
    int e = blockIdx.x * blockDim.x + threadIdx.x;
    if (e < N_EDGES) {
        int r = rows[e], c = cols[e];
        float a = adj[e];
        atomicAdd(&g_inv_drow[r], a);
        atomicAdd(&g_inv_dcol[c], a);
        atomicAdd(&g_cnt1[c], 1);   // support1 CSR keyed by dst = cols
        atomicAdd(&g_cnt2[r], 1);   // support2 CSR keyed by dst = rows
    }
}

// grid SCAN_BLKS x 1024: per-block exclusive scan of both histograms
// (local offsets into rowptr) + block totals; degree inversion in parallel.
__global__ void __launch_bounds__(1024) k_scan_local() {
    __shared__ int warp_sums[32];
    int t = threadIdx.x;
    int node = blockIdx.x * 1024 + t;
    int lane = t & 31;
    int warp = t >> 5;

    float d = g_inv_drow[node]; g_inv_drow[node] = (d > 0.f) ? (1.f / d) : 0.f;
    float c = g_inv_dcol[node]; g_inv_dcol[node] = (c > 0.f) ? (1.f / c) : 0.f;

    #pragma unroll
    for (int s = 0; s < 2; s++) {
        int v = s ? g_cnt2[node] : g_cnt1[node];
        int inc = v;
        #pragma unroll
        for (int off = 1; off < 32; off <<= 1) {
            int u = __shfl_up_sync(0xffffffffu, inc, off);
            if (lane >= off) inc += u;
        }
        if (lane == 31) warp_sums[warp] = inc;
        __syncthreads();
        if (warp == 0) {
            int w = warp_sums[lane];
            #pragma unroll
            for (int off = 1; off < 32; off <<= 1) {
                int u = __shfl_up_sync(0xffffffffu, w, off);
                if (lane >= off) w += u;
            }
            warp_sums[lane] = w;
        }
        __syncthreads();
        int excl = (inc - v) + (warp ? warp_sums[warp - 1] : 0);
        (s ? g_rowptr2 : g_rowptr1)[node] = excl;       // local (pre-offset)
        if (t == 1023) g_bsum[s][blockIdx.x] = warp_sums[31];
        __syncthreads();
    }
}

// grid 32 x 512: add block-prefix offsets, write final rowptr + pos
__global__ void __launch_bounds__(512) k_scan_apply() {
    __shared__ int off[2][SCAN_BLKS];
    int t = threadIdx.x;
    if (t < 2 * SCAN_BLKS) {
        int s = t >> 4, j = t & (SCAN_BLKS - 1);
        int sum = 0;
        for (int i = 0; i < j; i++) sum += g_bsum[s][i];
        off[s][j] = sum;
    }
    __syncthreads();

    int node = blockIdx.x * 512 + t;
    int b = node >> 10;
    int p1 = g_rowptr1[node] + off[0][b];
    int p2 = g_rowptr2[node] + off[1][b];
    g_rowptr1[node] = p1;  g_pos1[node] = p1;
    g_rowptr2[node] = p2;  g_pos2[node] = p2;
    if (node == 0) {
        g_rowptr1[N_NODES] = N_EDGES;
        g_rowptr2[N_NODES] = N_EDGES;
    }
}

__global__ void k_fill(const float* __restrict__ adj,
                       const int* __restrict__ rows,
                       const int* __restrict__ cols) {
    int e = blockIdx.x * blockDim.x + threadIdx.x;
    if (e < N_EDGES) {
        int r = rows[e], c = cols[e];
        float a = adj[e];
        int s1 = atomicAdd(&g_pos1[c], 1);
        g_adj_col[0][s1] = r;
        g_adj_val[0][s1] = a * g_inv_drow[r];
        int s2 = atomicAdd(&g_pos2[r], 1);
        g_adj_col[1][s2] = c;
        g_adj_val[1][s2] = a * g_inv_dcol[c];
    }
}

// transpose + fp32->fp16: x0[n, b*64+d] = inputs[b, n, d]
__global__ void k_transpose(const float* __restrict__ in) {
    int idx = blockIdx.x * blockDim.x + threadIdx.x;   // over N*FEAT/8
    int f8 = idx & 255;
    int n  = idx >> 8;
    int f  = f8 << 3;
    int b  = f >> 6;
    int d  = f & 63;
    const float4* src = reinterpret_cast<const float4*>(
        in + ((size_t)b * N_NODES * DIM + (size_t)n * DIM + d));
    float4 v0 = src[0];
    float4 v1 = src[1];
    __half2 h[4];
    h[0] = __floats2half2_rn(v0.x, v0.y);
    h[1] = __floats2half2_rn(v0.z, v0.w);
    h[2] = __floats2half2_rn(v1.x, v1.y);
    h[3] = __floats2half2_rn(v1.z, v1.w);
    *reinterpret_cast<uint4*>(&g_x[0][(size_t)n * FEAT + f]) =
        *reinterpret_cast<uint4*>(h);
}

// ---------------- SpMM (CSR gather, fp16 storage / fp32 accumulate) -------
// out = (S @ xin)            if m_z < 0
// out = 2*(S @ xin) - xz     otherwise
__global__ void __launch_bounds__(128)
k_spmm(int support, int m_in, int m_z, int m_out, int chunk, int streamout) {
    const int* __restrict__ rowptr = support ? g_rowptr2 : g_rowptr1;
    const int* __restrict__ colidx = g_adj_col[support];
    const float* __restrict__ val  = g_adj_val[support];
    const __half* __restrict__ xin = g_x[m_in];
    __half* __restrict__ xout      = g_x[m_out];

    int n = blockIdx.x;
    int fbase = chunk * FCHUNK + (threadIdx.x << 3);   // 8 halves per thread

    int e   = rowptr[n];
    int end = rowptr[n + 1];

    float acc[8];
    #pragma unroll
    for (int i = 0; i < 8; i++) acc[i] = 0.f;

    for (; e + 4 <= end; e += 4) {
        int   c0 = colidx[e],     c1 = colidx[e + 1];
        int   c2 = colidx[e + 2], c3 = colidx[e + 3];
        float v0 = val[e],     v1 = val[e + 1];
        float v2 = val[e + 2], v3 = val[e + 3];
        uint4 r0 = *reinterpret_cast<const uint4*>(xin + (size_t)c0 * FEAT + fbase);
        uint4 r1 = *reinterpret_cast<const uint4*>(xin + (size_t)c1 * FEAT + fbase);
        uint4 r2 = *reinterpret_cast<const uint4*>(xin + (size_t)c2 * FEAT + fbase);
        uint4 r3 = *reinterpret_cast<const uint4*>(xin + (size_t)c3 * FEAT + fbase);
        const __half2* h0 = reinterpret_cast<const __half2*>(&r0);
        const __half2* h1 = reinterpret_cast<const __half2*>(&r1);
        const __half2* h2 = reinterpret_cast<const __half2*>(&r2);
        const __half2* h3 = reinterpret_cast<const __half2*>(&r3);
        #pragma unroll
        for (int i = 0; i < 4; i++) {
            float2 f0 = __half22float2(h0[i]);
            float2 f1 = __half22float2(h1[i]);
            float2 f2 = __half22float2(h2[i]);
            float2 f3 = __half22float2(h3[i]);
            acc[2 * i]     += v0 * f0.x + v1 * f1.x + v2 * f2.x + v3 * f3.x;
            acc[2 * i + 1] += v0 * f0.y + v1 * f1.y + v2 * f2.y + v3 * f3.y;
        }
    }
    for (; e < end; e++) {
        int   c0 = colidx[e];
        float v0 = val[e];
        uint4 r0 = *reinterpret_cast<const uint4*>(xin + (size_t)c0 * FEAT + fbase);
        const __half2* h0 = reinterpret_cast<const __half2*>(&r0);
        #pragma unroll
        for (int i = 0; i < 4; i++) {
            float2 f0 = __half22float2(h0[i]);
            acc[2 * i]     += v0 * f0.x;
            acc[2 * i + 1] += v0 * f0.y;
        }
    }

    size_t ooff = (size_t)n * FEAT + fbase;
    if (m_z >= 0) {
        uint4 rz = __ldcs(reinterpret_cast<const uint4*>(g_x[m_z] + ooff));
        const __half2* hz = reinterpret_cast<const __half2*>(&rz);
        #pragma unroll
        for (int i = 0; i < 4; i++) {
            float2 fz = __half22float2(hz[i]);
            acc[2 * i]     = 2.f * acc[2 * i]     - fz.x;
            acc[2 * i + 1] = 2.f * acc[2 * i + 1] - fz.y;
        }
    }

    __half2 hout[4];
    #pragma unroll
    for (int i = 0; i < 4; i++)
        hout[i] = __floats2half2_rn(acc[2 * i], acc[2 * i + 1]);
    if (streamout)
        __stcs(reinterpret_cast<uint4*>(xout + ooff),
               *reinterpret_cast<uint4*>(hout));
    else
        *reinterpret_cast<uint4*>(xout + ooff) = *reinterpret_cast<uint4*>(hout);
}

// ---------------- tensor-core output GEMM (half of rows) -----------------
// out[row, :] = sum_{k'} A[row, k'] * Wh[k', :] + bias
//   row = b*N + n ; k' = m*64 + d ; A[row, k'] = g_x[m][n*FEAT + b*64 + d]
__global__ void __launch_bounds__(256)
k_gemm(const float* __restrict__ W, const float* __restrict__ bias,
       float* __restrict__ out, int row_base) {
    __shared__ __half swh[OUTD][WPAD];   // [n][k'], padded: 42 KB

    for (int i = threadIdx.x; i < WROWS * OUTD; i += 256) {
        int kp = i >> 6;          // k' = m*64+d
        int n  = i & 63;
        int d  = kp & 63;
        int m  = kp >> 6;
        swh[n][kp] = __float2half(W[(d * NMAT + m) * OUTD + n]);
    }
    __syncthreads();

    int warp = threadIdx.x >> 5;
    int lane = threadIdx.x & 31;
    int g = lane >> 2;            // 0..7
    int q = lane & 3;             // 0..3

    int rowbase = row_base + (blockIdx.x * 8 + warp) * 16;
    int b = rowbase >> 14;
    int node0 = rowbase & 16383;

    float acc[8][4];
    #pragma unroll
    for (int nt = 0; nt < 8; nt++) {
        float b0 = __ldg(bias + nt * 8 + 2 * q);
        float b1 = __ldg(bias + nt * 8 + 2 * q + 1);
        acc[nt][0] = b0; acc[nt][1] = b1;
        acc[nt][2] = b0; acc[nt][3] = b1;
    }

    #pragma unroll 1
    for (int m = 0; m < NMAT; m++) {
        const __half* xm = g_x[m] + (size_t)node0 * FEAT + b * DIM;
        #pragma unroll
        for (int ds = 0; ds < 4; ds++) {
            int d0 = ds * 16;
            const __half* base = xm + d0;
            unsigned a0 = *reinterpret_cast<const unsigned*>(base + (size_t)g * FEAT + 2 * q);
            unsigned a1 = *reinterpret_cast<const unsigned*>(base + (size_t)(g + 8) * FEAT + 2 * q);
            unsigned a2 = *reinterpret_cast<const unsigned*>(base + (size_t)g * FEAT + 2 * q + 8);
            unsigned a3 = *reinterpret_cast<const unsigned*>(base + (size_t)(g + 8) * FEAT + 2 * q + 8);
            int kp = m * 64 + d0;
            #pragma unroll
            for (int nt = 0; nt < 8; nt++) {
                int n = nt * 8 + g;
                unsigned b0 = *reinterpret_cast<const unsigned*>(&swh[n][kp + 2 * q]);
                unsigned b1 = *reinterpret_cast<const unsigned*>(&swh[n][kp + 2 * q + 8]);
                asm volatile(
                    "mma.sync.aligned.m16n8k16.row.col.f32.f16.f16.f32 "
                    "{%0,%1,%2,%3}, {%4,%5,%6,%7}, {%8,%9}, {%0,%1,%2,%3};\n"
                    : "+f"(acc[nt][0]), "+f"(acc[nt][1]),
                      "+f"(acc[nt][2]), "+f"(acc[nt][3])
                    : "r"(a0), "r"(a1), "r"(a2), "r"(a3), "r"(b0), "r"(b1));
            }
        }
    }

    #pragma unroll
    for (int nt = 0; nt < 8; nt++) {
        size_t o0 = (size_t)(rowbase + g) * OUTD + nt * 8 + 2 * q;
        size_t o1 = (size_t)(rowbase + g + 8) * OUTD + nt * 8 + 2 * q;
        *reinterpret_cast<float2*>(out + o0) = make_float2(acc[nt][0], acc[nt][1]);
        *reinterpret_cast<float2*>(out + o1) = make_float2(acc[nt][2], acc[nt][3]);
    }
}

// ---------------- launch ----------------
extern "C" void kernel_launch(void* const* d_in, const int* in_sizes, int n_in,
                              void* d_out, int out_size) {
    const float* inputs  = (const float*)d_in[0];
    const float* adj     = (const float*)d_in[1];
    const int*   rows    = (const int*)d_in[2];
    const int*   cols    = (const int*)d_in[3];
    const float* weights = (const float*)d_in[4];
    const float* biases  = (const float*)d_in[5];
    float*       out     = (float*)d_out;

    static cudaStream_t s2 = 0;
    static cudaEvent_t ev0 = 0, evT = 0, evJ = 0;
    static cudaEvent_t evC[2];
    if (!s2) {
        cudaStreamCreateWithFlags(&s2, cudaStreamNonBlocking);
        cudaEventCreateWithFlags(&ev0, cudaEventDisableTiming);
        cudaEventCreateWithFlags(&evT, cudaEventDisableTiming);
        cudaEventCreateWithFlags(&evJ, cudaEventDisableTiming);
        cudaEventCreateWithFlags(&evC[0], cudaEventDisableTiming);
        cudaEventCreateWithFlags(&evC[1], cudaEventDisableTiming);
    }

    // fork: transpose (writes g_x[0]) runs concurrent with CSR build
    cudaEventRecord(ev0, 0);
    cudaStreamWaitEvent(s2, ev0, 0);
    k_transpose<<<(N_NODES * (FEAT / 8)) / 256, 256, 0, s2>>>(inputs);
    cudaEventRecord(evT, s2);

    k_init<<<(N_NODES + 255) / 256, 256>>>();
    k_degree<<<N_EDGES / 256, 256>>>(adj, rows, cols);
    k_scan_local<<<SCAN_BLKS, 1024>>>();
    k_scan_apply<<<N_NODES / 512, 512>>>();
    k_fill<<<N_EDGES / 256, 256>>>(adj, rows, cols);
    cudaStreamWaitEvent(0, evT, 0);

    // chunk c covers batches 16c..16c+15; after chunk c's chain, GEMM rows
    // [c*HALF_ROWS, (c+1)*HALF_ROWS) are final -> overlap that GEMM half
    // with the next chunk's LTS-bound chain.
    for (int c = 0; c < FEAT / FCHUNK; c++) {
        // xs[1] = S1 @ x0
        k_spmm<<<N_NODES, 128>>>(0, 0, -1, 1, c, 0);
        // xs[2] = 2*S1@xs[1] - x0
        k_spmm<<<N_NODES, 128>>>(0, 1, 0, 2, c, 1);
        // xs[3] = S2 @ xs[1]   (x0 deliberately not reset between supports)
        k_spmm<<<N_NODES, 128>>>(1, 1, -1, 3, c, 0);
        // xs[4] = 2*S2@xs[3] - xs[1]
        k_spmm<<<N_NODES, 128>>>(1, 3, 1, 4, c, 1);
        cudaEventRecord(evC[c], 0);

        cudaStreamWaitEvent(s2, evC[c], 0);
        k_gemm<<<HALF_ROWS / 128, 256, 0, s2>>>(weights, biases, out,
                                                c * HALF_ROWS);
    }

    cudaEventRecord(evJ, s2);
    cudaStreamWaitEvent(0, evJ, 0);
}

// round 16
// speedup vs baseline: 1.0867x; 1.0289x over previous
#include <cuda_runtime.h>
#include <cuda_fp16.h>

// ---------------- problem constants ----------------
#define N_NODES 16384
#define N_EDGES 524288
#define BATCH   32
#define DIM     64
#define OUTD    64
#define FEAT    (BATCH * DIM)   /* 2048 */
#define NMAT    5
#define WROWS   (DIM * NMAT)    /* 320 */
#define NCHUNK  4
#define FCHUNK  (FEAT / NCHUNK) /* 512 halves per chunk */
#define WPAD    328             /* smem W row stride (halves), conflict-free */
#define ROWS_PER_Q (BATCH / NCHUNK * N_NODES)   /* 131072 GEMM rows/quarter */
#define SCAN_BLKS 16            /* blocks in k_scan_local (1024 nodes each) */

// ---------------- device scratch (static: no allocations allowed) ----------
__device__ __align__(16) __half g_x[NMAT][(size_t)N_NODES * FEAT];  // ~335 MB
__device__ float g_inv_drow[N_NODES];
__device__ float g_inv_dcol[N_NODES];
__device__ int   g_cnt1[N_NODES];
__device__ int   g_cnt2[N_NODES];
__device__ int   g_rowptr1[N_NODES + 1];
__device__ int   g_rowptr2[N_NODES + 1];
__device__ int   g_pos1[N_NODES];
__device__ int   g_pos2[N_NODES];
__device__ int   g_bsum[2][SCAN_BLKS];
__device__ int   g_adj_col[2][N_EDGES];
__device__ float g_adj_val[2][N_EDGES];

// ---------------- build kernels ----------------
__global__ void k_init() {
    int i = blockIdx.x * blockDim.x + threadIdx.x;
    if (i < N_NODES) {
        g_inv_drow[i] = 0.f;
        g_inv_dcol[i] = 0.f;
        g_cnt1[i] = 0;
        g_cnt2[i] = 0;
    }
}

__global__ void k_degree(const float* __restrict__ adj,
                         const int* __restrict__ rows,
                         const int* __restrict__ cols) {
    int e = blockIdx.x * blockDim.x + threadIdx.x;
    if (e < N_EDGES) {
        int r = rows[e], c = cols[e];
        float a = adj[e];
        atomicAdd(&g_inv_drow[r], a);
        atomicAdd(&g_inv_dcol[c], a);
        atomicAdd(&g_cnt1[c], 1);   // support1 CSR keyed by dst = cols
        atomicAdd(&g_cnt2[r], 1);   // support2 CSR keyed by dst = rows
    }
}

// grid SCAN_BLKS x 1024: per-block exclusive scan of both histograms
// (local offsets into rowptr) + block totals; degree inversion in parallel.
__global__ void __launch_bounds__(1024) k_scan_local() {
    __shared__ int warp_sums[32];
    int t = threadIdx.x;
    int node = blockIdx.x * 1024 + t;
    int lane = t & 31;
    int warp = t >> 5;

    float d = g_inv_drow[node]; g_inv_drow[node] = (d > 0.f) ? (1.f / d) : 0.f;
    float c = g_inv_dcol[node]; g_inv_dcol[node] = (c > 0.f) ? (1.f / c) : 0.f;

    #pragma unroll
    for (int s = 0; s < 2; s++) {
        int v = s ? g_cnt2[node] : g_cnt1[node];
        int inc = v;
        #pragma unroll
        for (int off = 1; off < 32; off <<= 1) {
            int u = __shfl_up_sync(0xffffffffu, inc, off);
            if (lane >= off) inc += u;
        }
        if (lane == 31) warp_sums[warp] = inc;
        __syncthreads();
        if (warp == 0) {
            int w = warp_sums[lane];
            #pragma unroll
            for (int off = 1; off < 32; off <<= 1) {
                int u = __shfl_up_sync(0xffffffffu, w, off);
                if (lane >= off) w += u;
            }
            warp_sums[lane] = w;
        }
        __syncthreads();
        int excl = (inc - v) + (warp ? warp_sums[warp - 1] : 0);
        (s ? g_rowptr2 : g_rowptr1)[node] = excl;       // local (pre-offset)
        if (t == 1023) g_bsum[s][blockIdx.x] = warp_sums[31];
        __syncthreads();
    }
}

// grid 32 x 512: add block-prefix offsets, write final rowptr + pos
__global__ void __launch_bounds__(512) k_scan_apply() {
    __shared__ int off[2][SCAN_BLKS];
    int t = threadIdx.x;
    if (t < 2 * SCAN_BLKS) {
        int s = t >> 4, j = t & (SCAN_BLKS - 1);
        int sum = 0;
        for (int i = 0; i < j; i++) sum += g_bsum[s][i];
        off[s][j] = sum;
    }
    __syncthreads();

    int node = blockIdx.x * 512 + t;
    int b = node >> 10;
    int p1 = g_rowptr1[node] + off[0][b];
    int p2 = g_rowptr2[node] + off[1][b];
    g_rowptr1[node] = p1;  g_pos1[node] = p1;
    g_rowptr2[node] = p2;  g_pos2[node] = p2;
    if (node == 0) {
        g_rowptr1[N_NODES] = N_EDGES;
        g_rowptr2[N_NODES] = N_EDGES;
    }
}

__global__ void k_fill(const float* __restrict__ adj,
                       const int* __restrict__ rows,
                       const int* __restrict__ cols) {
    int e = blockIdx.x * blockDim.x + threadIdx.x;
    if (e < N_EDGES) {
        int r = rows[e], c = cols[e];
        float a = adj[e];
        int s1 = atomicAdd(&g_pos1[c], 1);
        g_adj_col[0][s1] = r;
        g_adj_val[0][s1] = a * g_inv_drow[r];
        int s2 = atomicAdd(&g_pos2[r], 1);
        g_adj_col[1][s2] = c;
        g_adj_val[1][s2] = a * g_inv_dcol[c];
    }
}

// transpose + fp32->fp16: x0[n, b*64+d] = inputs[b, n, d]
__global__ void k_transpose(const float* __restrict__ in) {
    int idx = blockIdx.x * blockDim.x + threadIdx.x;   // over N*FEAT/8
    int f8 = idx & 255;
    int n  = idx >> 8;
    int f  = f8 << 3;
    int b  = f >> 6;
    int d  = f & 63;
    const float4* src = reinterpret_cast<const float4*>(
        in + ((size_t)b * N_NODES * DIM + (size_t)n * DIM + d));
    float4 v0 = src[0];
    float4 v1 = src[1];
    __half2 h[4];
    h[0] = __floats2half2_rn(v0.x, v0.y);
    h[1] = __floats2half2_rn(v0.z, v0.w);
    h[2] = __floats2half2_rn(v1.x, v1.y);
    h[3] = __floats2half2_rn(v1.z, v1.w);
    *reinterpret_cast<uint4*>(&g_x[0][(size_t)n * FEAT + f]) =
        *reinterpret_cast<uint4*>(h);
}

// ---------------- SpMM (CSR gather, fp16 storage / fp32 accumulate) -------
// out = (S @ xin)            if m_z < 0
// out = 2*(S @ xin) - xz     otherwise
__global__ void __launch_bounds__(64)
k_spmm(int support, int m_in, int m_z, int m_out, int chunk, int streamout) {
    const int* __restrict__ rowptr = support ? g_rowptr2 : g_rowptr1;
    const int* __restrict__ colidx = g_adj_col[support];
    const float* __restrict__ val  = g_adj_val[support];
    const __half* __restrict__ xin = g_x[m_in];
    __half* __restrict__ xout      = g_x[m_out];

    int n = blockIdx.x;
    int fbase = chunk * FCHUNK + (threadIdx.x << 3);   // 8 halves per thread

    int e   = rowptr[n];
    int end = rowptr[n + 1];

    float acc[8];
    #pragma unroll
    for (int i = 0; i < 8; i++) acc[i] = 0.f;

    for (; e + 4 <= end; e += 4) {
        int   c0 = colidx[e],     c1 = colidx[e + 1];
        int   c2 = colidx[e + 2], c3 = colidx[e + 3];
        float v0 = val[e],     v1 = val[e + 1];
        float v2 = val[e + 2], v3 = val[e + 3];
        uint4 r0 = *reinterpret_cast<const uint4*>(xin + (size_t)c0 * FEAT + fbase);
        uint4 r1 = *reinterpret_cast<const uint4*>(xin + (size_t)c1 * FEAT + fbase);
        uint4 r2 = *reinterpret_cast<const uint4*>(xin + (size_t)c2 * FEAT + fbase);
        uint4 r3 = *reinterpret_cast<const uint4*>(xin + (size_t)c3 * FEAT + fbase);
        const __half2* h0 = reinterpret_cast<const __half2*>(&r0);
        const __half2* h1 = reinterpret_cast<const __half2*>(&r1);
        const __half2* h2 = reinterpret_cast<const __half2*>(&r2);
        const __half2* h3 = reinterpret_cast<const __half2*>(&r3);
        #pragma unroll
        for (int i = 0; i < 4; i++) {
            float2 f0 = __half22float2(h0[i]);
            float2 f1 = __half22float2(h1[i]);
            float2 f2 = __half22float2(h2[i]);
            float2 f3 = __half22float2(h3[i]);
            acc[2 * i]     += v0 * f0.x + v1 * f1.x + v2 * f2.x + v3 * f3.x;
            acc[2 * i + 1] += v0 * f0.y + v1 * f1.y + v2 * f2.y + v3 * f3.y;
        }
    }
    for (; e < end; e++) {
        int   c0 = colidx[e];
        float v0 = val[e];
        uint4 r0 = *reinterpret_cast<const uint4*>(xin + (size_t)c0 * FEAT + fbase);
        const __half2* h0 = reinterpret_cast<const __half2*>(&r0);
        #pragma unroll
        for (int i = 0; i < 4; i++) {
            float2 f0 = __half22float2(h0[i]);
            acc[2 * i]     += v0 * f0.x;
            acc[2 * i + 1] += v0 * f0.y;
        }
    }

    size_t ooff = (size_t)n * FEAT + fbase;
    if (m_z >= 0) {
        uint4 rz = __ldcs(reinterpret_cast<const uint4*>(g_x[m_z] + ooff));
        const __half2* hz = reinterpret_cast<const __half2*>(&rz);
        #pragma unroll
        for (int i = 0; i < 4; i++) {
            float2 fz = __half22float2(hz[i]);
            acc[2 * i]     = 2.f * acc[2 * i]     - fz.x;
            acc[2 * i + 1] = 2.f * acc[2 * i + 1] - fz.y;
        }
    }

    __half2 hout[4];
    #pragma unroll
    for (int i = 0; i < 4; i++)
        hout[i] = __floats2half2_rn(acc[2 * i], acc[2 * i + 1]);
    if (streamout)
        __stcs(reinterpret_cast<uint4*>(xout + ooff),
               *reinterpret_cast<uint4*>(hout));
    else
        *reinterpret_cast<uint4*>(xout + ooff) = *reinterpret_cast<uint4*>(hout);
}

// ---------------- tensor-core output GEMM (quarter of rows) ---------------
// out[row, :] = sum_{k'} A[row, k'] * Wh[k', :] + bias
//   row = b*N + n ; k' = m*64 + d ; A[row, k'] = g_x[m][n*FEAT + b*64 + d]
__global__ void __launch_bounds__(256)
k_gemm(const float* __restrict__ W, const float* __restrict__ bias,
       float* __restrict__ out, int row_base) {
    __shared__ __half swh[OUTD][WPAD];   // [n][k'], padded: 42 KB

    for (int i = threadIdx.x; i < WROWS * OUTD; i += 256) {
        int kp = i >> 6;          // k' = m*64+d
        int n  = i & 63;
        int d  = kp & 63;
        int m  = kp >> 6;
        swh[n][kp] = __float2half(W[(d * NMAT + m) * OUTD + n]);
    }
    __syncthreads();

    int warp = threadIdx.x >> 5;
    int lane = threadIdx.x & 31;
    int g = lane >> 2;            // 0..7
    int q = lane & 3;             // 0..3

    int rowbase = row_base + (blockIdx.x * 8 + warp) * 16;
    int b = rowbase >> 14;
    int node0 = rowbase & 16383;

    float acc[8][4];
    #pragma unroll
    for (int nt = 0; nt < 8; nt++) {
        float b0 = __ldg(bias + nt * 8 + 2 * q);
        float b1 = __ldg(bias + nt * 8 + 2 * q + 1);
        acc[nt][0] = b0; acc[nt][1] = b1;
        acc[nt][2] = b0; acc[nt][3] = b1;
    }

    #pragma unroll 1
    for (int m = 0; m < NMAT; m++) {
        const __half* xm = g_x[m] + (size_t)node0 * FEAT + b * DIM;
        #pragma unroll
        for (int ds = 0; ds < 4; ds++) {
            int d0 = ds * 16;
            const __half* base = xm + d0;
            unsigned a0 = *reinterpret_cast<const unsigned*>(base + (size_t)g * FEAT + 2 * q);
            unsigned a1 = *reinterpret_cast<const unsigned*>(base + (size_t)(g + 8) * FEAT + 2 * q);
            unsigned a2 = *reinterpret_cast<const unsigned*>(base + (size_t)g * FEAT + 2 * q + 8);
            unsigned a3 = *reinterpret_cast<const unsigned*>(base + (size_t)(g + 8) * FEAT + 2 * q + 8);
            int kp = m * 64 + d0;
            #pragma unroll
            for (int nt = 0; nt < 8; nt++) {
                int n = nt * 8 + g;
                unsigned b0 = *reinterpret_cast<const unsigned*>(&swh[n][kp + 2 * q]);
                unsigned b1 = *reinterpret_cast<const unsigned*>(&swh[n][kp + 2 * q + 8]);
                asm volatile(
                    "mma.sync.aligned.m16n8k16.row.col.f32.f16.f16.f32 "
                    "{%0,%1,%2,%3}, {%4,%5,%6,%7}, {%8,%9}, {%0,%1,%2,%3};\n"
                    : "+f"(acc[nt][0]), "+f"(acc[nt][1]),
                      "+f"(acc[nt][2]), "+f"(acc[nt][3])
                    : "r"(a0), "r"(a1), "r"(a2), "r"(a3), "r"(b0), "r"(b1));
            }
        }
    }

    #pragma unroll
    for (int nt = 0; nt < 8; nt++) {
        size_t o0 = (size_t)(rowbase + g) * OUTD + nt * 8 + 2 * q;
        size_t o1 = (size_t)(rowbase + g + 8) * OUTD + nt * 8 + 2 * q;
        *reinterpret_cast<float2*>(out + o0) = make_float2(acc[nt][0], acc[nt][1]);
        *reinterpret_cast<float2*>(out + o1) = make_float2(acc[nt][2], acc[nt][3]);
    }
}

// ---------------- launch (dual-stream chunk chains) ----------------
extern "C" void kernel_launch(void* const* d_in, const int* in_sizes, int n_in,
                              void* d_out, int out_size) {
    const float* inputs  = (const float*)d_in[0];
    const float* adj     = (const float*)d_in[1];
    const int*   rows    = (const int*)d_in[2];
    const int*   cols    = (const int*)d_in[3];
    const float* weights = (const float*)d_in[4];
    const float* biases  = (const float*)d_in[5];
    float*       out     = (float*)d_out;

    static cudaStream_t s2 = 0;
    static cudaEvent_t ev0 = 0, evT = 0, evB = 0, evJ = 0;
    if (!s2) {
        cudaStreamCreateWithFlags(&s2, cudaStreamNonBlocking);
        cudaEventCreateWithFlags(&ev0, cudaEventDisableTiming);
        cudaEventCreateWithFlags(&evT, cudaEventDisableTiming);
        cudaEventCreateWithFlags(&evB, cudaEventDisableTiming);
        cudaEventCreateWithFlags(&evJ, cudaEventDisableTiming);
    }

    // fork: transpose (writes g_x[0]) runs concurrent with CSR build
    cudaEventRecord(ev0, 0);
    cudaStreamWaitEvent(s2, ev0, 0);
    k_transpose<<<(N_NODES * (FEAT / 8)) / 256, 256, 0, s2>>>(inputs);
    cudaEventRecord(evT, s2);

    k_init<<<(N_NODES + 255) / 256, 256>>>();
    k_degree<<<N_EDGES / 256, 256>>>(adj, rows, cols);
    k_scan_local<<<SCAN_BLKS, 1024>>>();
    k_scan_apply<<<N_NODES / 512, 512>>>();
    k_fill<<<N_EDGES / 256, 256>>>(adj, rows, cols);
    cudaStreamWaitEvent(0, evT, 0);
    cudaEventRecord(evB, 0);     // build + x0 ready
    cudaStreamWaitEvent(s2, evB, 0);

    // chunk c covers batches 8c..8c+7 (feature-disjoint) -> chains are fully
    // independent. Even chunks on main stream, odd on s2: two concurrent
    // LTS-saturated chains fill each other's launch ramps; each chunk's
    // quarter-GEMM follows on its own stream and hides in the other chain.
    for (int c = 0; c < NCHUNK; c++) {
        cudaStream_t s = (c & 1) ? s2 : (cudaStream_t)0;
        // xs[1] = S1 @ x0
        k_spmm<<<N_NODES, 64, 0, s>>>(0, 0, -1, 1, c, 0);
        // xs[2] = 2*S1@xs[1] - x0
        k_spmm<<<N_NODES, 64, 0, s>>>(0, 1, 0, 2, c, 1);
        // xs[3] = S2 @ xs[1]   (x0 deliberately not reset between supports)
        k_spmm<<<N_NODES, 64, 0, s>>>(1, 1, -1, 3, c, 0);
        // xs[4] = 2*S2@xs[3] - xs[1]
        k_spmm<<<N_NODES, 64, 0, s>>>(1, 3, 1, 4, c, 1);
        k_gemm<<<ROWS_PER_Q / 128, 256, 0, s>>>(weights, biases, out,
                                                c * ROWS_PER_Q);
    }

    // join
    cudaEventRecord(evJ, s2);
    cudaStreamWaitEvent(0, evJ, 0);
}